// round 14
// baseline (speedup 1.0000x reference)
#include <cuda_runtime.h>
#include <cstring>

#define GN 512
#define TBR 64          // tile rows
#define TBC 32          // tile cols
#define TD 8            // max temporal depth per launch
#define ROWS_P 82       // padded smem rows (region 80 + ring)
#define COLS_P 56       // float stride: conflict-free LDS.128
#define NGRP 12         // 4-column groups per region (48 cols)
#define NT 480          // 12 groups x 40 two-row strips = 15 warps
#define NWARP 15
#define TOTAL_STEPS 199

typedef unsigned long long u64;
typedef ulonglong2 V4;

__device__ __forceinline__ u64 PKf(float a, float b) {
    float2 t = make_float2(a, b); u64 r; memcpy(&r, &t, 8); return r;
}
__device__ __forceinline__ float2 UPf(u64 v) {
    float2 t; memcpy(&t, &v, 8); return t;
}
__device__ __forceinline__ u64 ADD2(u64 a, u64 b) {
    u64 d; asm("add.rn.f32x2 %0,%1,%2;" : "=l"(d) : "l"(a), "l"(b)); return d;
}
__device__ __forceinline__ u64 MUL2(u64 a, u64 b) {
    u64 d; asm("mul.rn.f32x2 %0,%1,%2;" : "=l"(d) : "l"(a), "l"(b)); return d;
}
__device__ __forceinline__ u64 FMA2(u64 a, u64 b, u64 c) {
    u64 d; asm("fma.rn.f32x2 %0,%1,%2,%3;" : "=l"(d) : "l"(a), "l"(b), "l"(c)); return d;
}

// new(i,j) = V(clamp(i,1,510), clamp(j,1,510)); state extended by clamp(.,0,511).
// 64x32 tiles -> 128 CTAs (one per SM), PDL-chained chunks of TD steps, fused LDG
// step 0, garbage-ringed 80x48 region, f32x2 math on LDS.128 pairs, branchless
// col specials, same-thread row fixups, last step skips STS.
// THIS ROUND: the per-step __syncthreads (convoy) is replaced by per-warp
// dataflow flags. Warp w's step-t stencil window spans thread ids +/-13, i.e.
// warps w-1..w+1 only; it spins on wflag[w+/-1] >= t-1 and posts wflag[w]=t
// after its fenced STS. Warps pipeline with diagonal skew. Ping-pong safety:
// flag order covers all w+/-1 hazards; w/w+2 concurrency (skew<=2) touches
// provably disjoint rows (ty_min(w+2)-ty_max(w)=3 for all w).
template <int NSTEPS>
__global__ __launch_bounds__(NT) void adr_chunk(
    const float* __restrict__ in_state,
    float* __restrict__ frames,
    const float* __restrict__ k1p, const float* __restrict__ k2p,
    const float* __restrict__ a1p, const float* __restrict__ a2p)
{
    __shared__ __align__(16) float buf[2][ROWS_P][COLS_P];
    __shared__ int wflag[NWARP + 1];

    // ---------- preamble: before the PDL fence ----------
    const float k1 = __ldg(k1p), k2 = __ldg(k2p);
    const float a1 = __ldg(a1p), a2 = __ldg(a2p);
    const float inv_k12 = 1.0f / (k1 + k2);
    const float inv_dx2 = 511.0f * 511.0f;
    const float inv_2dx = 255.5f;
    const float DTC = 1e-7f;

    const int by = blockIdx.y, bx = blockIdx.x;
    const int r0 = by * TBR - TD;
    const int c0 = bx * TBC - TD;
    const int tid = (int)threadIdx.x;
    const int w   = tid >> 5;
    const int wm  = max(w - 1, 0);
    const int wp  = min(w + 1, NWARP - 1);
    const bool lane0 = ((tid & 31) == 0);
    const int g  = tid % NGRP;
    const int ty = tid / NGRP;
    const int rbase = ty * 2;
    const int gj0 = c0 + 4 * g;
    const int sc  = 4 * g + 4;

    const float kap = (gj0 < 256) ? k1 : k2;
    const float al  = (gj0 < 256) ? a1 : a2;

    const float A1c = DTC * al * inv_dx2;
    const u64 cA1    = PKf(A1c, A1c);
    const u64 c1M4A1 = PKf(1.0f - 4.0f * A1c, 1.0f - 4.0f * A1c);
    const u64 cM1    = PKf(-1.0f, -1.0f);
    const u64 cONE   = PKf(1.0f, 1.0f);
    const u64 cI2    = PKf(inv_2dx, inv_2dx);
    const u64 cMI2   = PKf(-inv_2dx, -inv_2dx);
    const u64 cB1    = PKf(DTC * kap, DTC * kap);

    const bool colC = (g >= 2) && (g <= 9);
    const bool rowC = (ty >= 4) && (ty <= 35);
    const bool storeC = colC && rowC;
    const bool isI  = (gj0 == 252);
    const bool isL  = (gj0 == 0);
    const bool isR  = (gj0 == 508);
    const bool topFix = (by == 0) && (ty == 4);
    const bool botFix = (by == GN / TBR - 1) && (ty == 35);

    auto pointPair = [&](u64 Tm, u64 Tc, u64 Tp, u64 L, u64 R) -> u64 {
        u64 sum  = ADD2(ADD2(Tm, Tp), ADD2(L, R));
        u64 lapc = FMA2(Tc, c1M4A1, MUL2(sum, cA1));
        u64 dxv  = FMA2(Tm, cM1, Tp);
        u64 dyv  = FMA2(L,  cM1, R);
        u64 P    = FMA2(dxv, cMI2, ADD2(Tc, cM1));
        u64 Q    = FMA2(dyv, cI2,  cONE);
        u64 S    = FMA2(MUL2(Tc, Tc), P, MUL2(Tc, Q));
        return FMA2(S, cB1, lapc);
    };

    auto rowcalc = [&](V4 Fm, V4 Fc, V4 Fp, float TlS, float TrS) -> V4 {
        float2 cl = UPf(Fc.x);
        float2 ch = UPf(Fc.y);
        u64 L0 = PKf(TlS, cl.x);
        u64 M  = PKf(cl.y, ch.x);
        u64 R1 = PKf(ch.y, TrS);
        u64 v0 = pointPair(Fm.x, Fc.x, Fp.x, L0, M);
        u64 v1 = pointPair(Fm.y, Fc.y, Fp.y, M, R1);
        float2 vh = UPf(v1);
        float ifv = fmaf(k1, TrS, k2 * ch.x) * inv_k12;  // interface col 255
        vh.y = isI ? ifv : vh.y;
        vh.y = isR ? vh.x : vh.y;                         // col 511 := 510
        v1 = PKf(vh.x, vh.y);
        float2 vl = UPf(v0);
        vl.x = isL ? vl.y : vl.x;                         // col 0 := 1
        v0 = PKf(vl.x, vl.y);
        V4 out; out.x = v0; out.y = v1; return out;
    };

    float* const fr0 = frames + (ptrdiff_t)(r0 + rbase) * GN + gj0;

    const bool canVec = (gj0 >= 0) && (gj0 + 3 < GN);
    const int j0 = min(max(gj0 + 0, 0), GN - 1);
    const int j1 = min(max(gj0 + 1, 0), GN - 1);
    const int j2 = min(max(gj0 + 2, 0), GN - 1);
    const int j3 = min(max(gj0 + 3, 0), GN - 1);
    const int jl = min(max(gj0 - 1, 0), GN - 1);
    const int jr = min(max(gj0 + 4, 0), GN - 1);

    // flag init (once per launch; smem is fresh each launch)
    if (tid < NWARP) wflag[tid] = -1;
    __syncthreads();

    volatile int* vf = wflag;

    // post: make this warp's step-s smem writes visible, then raise flag
    auto post = [&](int s) {
        __syncwarp();
        if (lane0) {
            __threadfence_block();   // cumulativity: warp's writes (observed via
            vf[w] = s;               // syncwarp) ordered before the flag store
        }
    };
    // wait: neighbors finished step `need`
    auto waitnb = [&](int need) {
        while (vf[wm] < need || vf[wp] < need) { }
        __threadfence_block();       // acquire: order subsequent LDS after spin
    };

    // ---------- PDL fence: predecessor's final frame must be visible ----------
#if __CUDA_ARCH__ >= 900
    cudaGridDependencySynchronize();
#endif

    // ================= fused global load + STEP 0 =================
    {
        auto ldrow = [&](int gi) -> V4 {
            int li = min(max(gi, 0), GN - 1);
            if (canVec) return *(const V4*)&in_state[(size_t)li * GN + gj0];
            V4 v;
            v.x = PKf(in_state[(size_t)li * GN + j0], in_state[(size_t)li * GN + j1]);
            v.y = PKf(in_state[(size_t)li * GN + j2], in_state[(size_t)li * GN + j3]);
            return v;
        };
        auto lded = [&](int gi, int jj) -> float {
            int li = min(max(gi, 0), GN - 1);
            return in_state[(size_t)li * GN + jj];
        };

        V4 Fm = ldrow(r0 + rbase - 1);
        V4 F1 = ldrow(r0 + rbase);
        V4 F2 = ldrow(r0 + rbase + 1);
        V4 F3 = ldrow(r0 + rbase + 2);
        float TlA = lded(r0 + rbase,     jl), TrA = lded(r0 + rbase,     jr);
        float TlB = lded(r0 + rbase + 1, jl), TrB = lded(r0 + rbase + 1, jr);

        V4 VA = rowcalc(Fm, F1, F2, TlA, TrA);
        V4 VB = rowcalc(F1, F2, F3, TlB, TrB);

        *(V4*)&buf[0][rbase + 1][sc] = VA;
        *(V4*)&buf[0][rbase + 2][sc] = VB;
        if (storeC) {
            *(V4*)&fr0[0]  = VA;
            *(V4*)&fr0[GN] = VB;
        }
        if (topFix) {
            *(V4*)&buf[0][9][sc] = VB;
            if (colC) *(V4*)&frames[gj0] = VB;
        }
        if (botFix) {
            *(V4*)&buf[0][72][sc] = VA;
            if (colC) *(V4*)&frames[(size_t)(GN - 1) * GN + gj0] = VA;
        }
    }
    post(0);

    // ================= steps 1 .. NSTEPS-1 (warp-dataflow ping-pong) =================
    #pragma unroll
    for (int s = 1; s < NSTEPS; ++s) {
        const float (*A)[COLS_P] = buf[(s + 1) & 1];
        float (*B)[COLS_P] = buf[s & 1];
        float* f0 = fr0 + (size_t)s * (GN * GN);
        const bool last = (s == NSTEPS - 1);

        waitnb(s - 1);

        V4 F0 = *(const V4*)&A[rbase + 0][sc];
        V4 F1 = *(const V4*)&A[rbase + 1][sc];
        V4 F2 = *(const V4*)&A[rbase + 2][sc];
        V4 F3 = *(const V4*)&A[rbase + 3][sc];
        float TlA = A[rbase + 1][sc - 1], TrA = A[rbase + 1][sc + 4];
        float TlB = A[rbase + 2][sc - 1], TrB = A[rbase + 2][sc + 4];

        V4 VA = rowcalc(F0, F1, F2, TlA, TrA);
        V4 VB = rowcalc(F1, F2, F3, TlB, TrB);

        if (!last) {
            *(V4*)&B[rbase + 1][sc] = VA;
            *(V4*)&B[rbase + 2][sc] = VB;
        }
        if (storeC) {
            *(V4*)&f0[0]  = VA;
            *(V4*)&f0[GN] = VB;
        }
        if (topFix) {
            if (!last) *(V4*)&B[9][sc] = VB;
            if (colC) *(V4*)&frames[(size_t)s * (GN * GN) + gj0] = VB;
        }
        if (botFix) {
            if (!last) *(V4*)&B[72][sc] = VA;
            if (colC) *(V4*)&frames[(size_t)s * (GN * GN) + (size_t)(GN - 1) * GN + gj0] = VA;
        }
        if (!last) post(s);
    }

#if __CUDA_ARCH__ >= 900
    cudaTriggerProgrammaticLaunchCompletion();
#endif
}

static void launch_pdl(const void* func, const float* src, float* dst,
                       const float* k1, const float* k2,
                       const float* a1, const float* a2)
{
    cudaLaunchConfig_t cfg = {};
    cfg.gridDim  = dim3(GN / TBC, GN / TBR);   // 16 x 8 = 128 CTAs
    cfg.blockDim = dim3(NT);
    cfg.dynamicSmemBytes = 0;
    cfg.stream = 0;
    cudaLaunchAttribute attr[1];
    attr[0].id = cudaLaunchAttributeProgrammaticStreamSerialization;
    attr[0].val.programmaticStreamSerializationAllowed = 1;
    cfg.attrs = attr;
    cfg.numAttrs = 1;
    void* args[] = { (void*)&src, (void*)&dst, (void*)&k1, (void*)&k2,
                     (void*)&a1, (void*)&a2 };
    cudaLaunchKernelExC(&cfg, func, args);
}

extern "C" void kernel_launch(void* const* d_in, const int* in_sizes, int n_in,
                              void* d_out, int out_size)
{
    (void)in_sizes; (void)n_in; (void)out_size;
    const float* u0 = (const float*)d_in[0];
    const float* k1 = (const float*)d_in[1];
    const float* k2 = (const float*)d_in[2];
    const float* a1 = (const float*)d_in[3];
    const float* a2 = (const float*)d_in[4];
    float* out = (float*)d_out;

    int done = 0;
    const float* src = u0;
    while (done < TOTAL_STEPS) {
        int steps = TOTAL_STEPS - done;
        if (steps >= TD) {
            launch_pdl((const void*)adr_chunk<TD>, src,
                       out + (size_t)done * GN * GN, k1, k2, a1, a2);
            steps = TD;
        } else {
            launch_pdl((const void*)adr_chunk<TD - 1>, src,
                       out + (size_t)done * GN * GN, k1, k2, a1, a2);
        }
        src = out + (size_t)(done + steps - 1) * GN * GN;
        done += steps;
    }
}

// round 15
// speedup vs baseline: 1.0838x; 1.0838x over previous
#include <cuda_runtime.h>
#include <cstring>

#define GN 512
#define TBR 32          // tile rows
#define TBC 32          // tile cols
#define TD 8            // max temporal depth per launch
#define ROWS_P 50       // padded smem rows (region 48 + ring)
#define COLS_P 56       // float stride: 2-row offset 112 = 16 mod 32 -> conflict-free LDS.128
#define NGRP 12         // 4-column groups per region (48 cols)
#define NT 288          // 12 groups x 24 two-row strips = 9 warps
#define TOTAL_STEPS 199

typedef unsigned long long u64;
typedef ulonglong2 V4;

__device__ __forceinline__ u64 PKf(float a, float b) {
    float2 t = make_float2(a, b); u64 r; memcpy(&r, &t, 8); return r;
}
__device__ __forceinline__ float2 UPf(u64 v) {
    float2 t; memcpy(&t, &v, 8); return t;
}
__device__ __forceinline__ u64 ADD2(u64 a, u64 b) {
    u64 d; asm("add.rn.f32x2 %0,%1,%2;" : "=l"(d) : "l"(a), "l"(b)); return d;
}
__device__ __forceinline__ u64 MUL2(u64 a, u64 b) {
    u64 d; asm("mul.rn.f32x2 %0,%1,%2;" : "=l"(d) : "l"(a), "l"(b)); return d;
}
__device__ __forceinline__ u64 FMA2(u64 a, u64 b, u64 c) {
    u64 d; asm("fma.rn.f32x2 %0,%1,%2,%3;" : "=l"(d) : "l"(a), "l"(b), "l"(c)); return d;
}

// new(i,j) = V(clamp(i,1,510), clamp(j,1,510)); state extended by clamp(.,0,511).
// THIS ROUND: 32x32 tiles -> 16x16 = 256 CTAs, TWO independent hardware CTAs per
// SM (separate register files + barriers) so barrier-drain/LDS-ramp phases of one
// CTA are covered by the other's compute -- the overlap R10/R14's software
// schemes couldn't deliver. Region 48x48 recomputed per step in a garbage-ringed
// smem buffer (fused LDG step 0 -> erosion starts at step 1; central 32x32 exact
// for 8 steps). f32x2 math on LDS.128 pairs, branchless col specials, same-thread
// row fixups (by==0,ty==4 owns global rows 0,1; by==15,ty==19 owns 510,511),
// last step skips STS+barrier, PDL chains chunks.
template <int NSTEPS>
__global__ __launch_bounds__(NT) void adr_chunk(
    const float* __restrict__ in_state,
    float* __restrict__ frames,
    const float* __restrict__ k1p, const float* __restrict__ k2p,
    const float* __restrict__ a1p, const float* __restrict__ a2p)
{
    __shared__ __align__(16) float buf[2][ROWS_P][COLS_P];

    // ---------- preamble: before the PDL fence ----------
    const float k1 = __ldg(k1p), k2 = __ldg(k2p);
    const float a1 = __ldg(a1p), a2 = __ldg(a2p);
    const float inv_k12 = 1.0f / (k1 + k2);
    const float inv_dx2 = 511.0f * 511.0f;
    const float inv_2dx = 255.5f;
    const float DTC = 1e-7f;

    const int by = blockIdx.y, bx = blockIdx.x;
    const int r0 = by * TBR - TD;
    const int c0 = bx * TBC - TD;
    const int tid = (int)threadIdx.x;
    const int g  = tid % NGRP;                 // 4-col group 0..11
    const int ty = tid / NGRP;                 // strip 0..23 (2 rows)
    const int rbase = ty * 2;
    const int gj0 = c0 + 4 * g;
    const int sc  = 4 * g + 4;                 // smem col (16B aligned)

    const float kap = (gj0 < 256) ? k1 : k2;   // 4 | 256: never straddles
    const float al  = (gj0 < 256) ? a1 : a2;

    const float A1c = DTC * al * inv_dx2;
    const u64 cA1    = PKf(A1c, A1c);
    const u64 c1M4A1 = PKf(1.0f - 4.0f * A1c, 1.0f - 4.0f * A1c);
    const u64 cM1    = PKf(-1.0f, -1.0f);
    const u64 cONE   = PKf(1.0f, 1.0f);
    const u64 cI2    = PKf(inv_2dx, inv_2dx);
    const u64 cMI2   = PKf(-inv_2dx, -inv_2dx);
    const u64 cB1    = PKf(DTC * kap, DTC * kap);

    const bool colC = (g >= 2) && (g <= 9);            // central 32 cols
    const bool rowC = (ty >= 4) && (ty <= 19);         // central 32 rows
    const bool storeC = colC && rowC;
    const bool isI  = (gj0 == 252);                    // group holding col 255
    const bool isL  = (gj0 == 0);
    const bool isR  = (gj0 == 508);                    // group holding col 511
    const bool topFix = (by == 0) && (ty == 4);            // global rows 0,1
    const bool botFix = (by == GN / TBR - 1) && (ty == 19); // global rows 510,511

    auto pointPair = [&](u64 Tm, u64 Tc, u64 Tp, u64 L, u64 R) -> u64 {
        u64 sum  = ADD2(ADD2(Tm, Tp), ADD2(L, R));
        u64 lapc = FMA2(Tc, c1M4A1, MUL2(sum, cA1));   // Tc + DT*al*lap
        u64 dxv  = FMA2(Tm, cM1, Tp);                   // Tp - Tm
        u64 dyv  = FMA2(L,  cM1, R);                    // R - L
        u64 P    = FMA2(dxv, cMI2, ADD2(Tc, cM1));      // (c-1) - T_x
        u64 Q    = FMA2(dyv, cI2,  cONE);               // T_y + 1
        u64 S    = FMA2(MUL2(Tc, Tc), P, MUL2(Tc, Q));  // c^2*P + c*Q
        return FMA2(S, cB1, lapc);
    };

    auto rowcalc = [&](V4 Fm, V4 Fc, V4 Fp, float TlS, float TrS) -> V4 {
        float2 cl = UPf(Fc.x);
        float2 ch = UPf(Fc.y);
        u64 L0 = PKf(TlS, cl.x);
        u64 M  = PKf(cl.y, ch.x);              // R of pair0 == L of pair1
        u64 R1 = PKf(ch.y, TrS);
        u64 v0 = pointPair(Fm.x, Fc.x, Fp.x, L0, M);
        u64 v1 = pointPair(Fm.y, Fc.y, Fp.y, M, R1);
        float2 vh = UPf(v1);
        float ifv = fmaf(k1, TrS, k2 * ch.x) * inv_k12;  // interface col 255
        vh.y = isI ? ifv : vh.y;
        vh.y = isR ? vh.x : vh.y;                         // col 511 := 510
        v1 = PKf(vh.x, vh.y);
        float2 vl = UPf(v0);
        vl.x = isL ? vl.y : vl.x;                         // col 0 := 1
        v0 = PKf(vl.x, vl.y);
        V4 out; out.x = v0; out.y = v1; return out;
    };

    float* const fr0 = frames + (ptrdiff_t)(r0 + rbase) * GN + gj0;

    const bool canVec = (gj0 >= 0) && (gj0 + 3 < GN);
    const int j0 = min(max(gj0 + 0, 0), GN - 1);
    const int j1 = min(max(gj0 + 1, 0), GN - 1);
    const int j2 = min(max(gj0 + 2, 0), GN - 1);
    const int j3 = min(max(gj0 + 3, 0), GN - 1);
    const int jl = min(max(gj0 - 1, 0), GN - 1);
    const int jr = min(max(gj0 + 4, 0), GN - 1);

    // ---------- PDL fence: predecessor's final frame must be visible ----------
#if __CUDA_ARCH__ >= 900
    cudaGridDependencySynchronize();
#endif

    // ================= fused global load + STEP 0 =================
    {
        auto ldrow = [&](int gi) -> V4 {
            int li = min(max(gi, 0), GN - 1);
            if (canVec) return *(const V4*)&in_state[(size_t)li * GN + gj0];
            V4 v;
            v.x = PKf(in_state[(size_t)li * GN + j0], in_state[(size_t)li * GN + j1]);
            v.y = PKf(in_state[(size_t)li * GN + j2], in_state[(size_t)li * GN + j3]);
            return v;
        };
        auto lded = [&](int gi, int jj) -> float {
            int li = min(max(gi, 0), GN - 1);
            return in_state[(size_t)li * GN + jj];
        };

        V4 Fm = ldrow(r0 + rbase - 1);
        V4 F1 = ldrow(r0 + rbase);
        V4 F2 = ldrow(r0 + rbase + 1);
        V4 F3 = ldrow(r0 + rbase + 2);
        float TlA = lded(r0 + rbase,     jl), TrA = lded(r0 + rbase,     jr);
        float TlB = lded(r0 + rbase + 1, jl), TrB = lded(r0 + rbase + 1, jr);

        V4 VA = rowcalc(Fm, F1, F2, TlA, TrA);
        V4 VB = rowcalc(F1, F2, F3, TlB, TrB);

        *(V4*)&buf[0][rbase + 1][sc] = VA;
        *(V4*)&buf[0][rbase + 2][sc] = VB;
        if (storeC) {
            *(V4*)&fr0[0]  = VA;
            *(V4*)&fr0[GN] = VB;
        }
        if (topFix) {               // global row 0 := row 1
            *(V4*)&buf[0][9][sc] = VB;
            if (colC) *(V4*)&frames[gj0] = VB;
        }
        if (botFix) {               // global row 511 := row 510
            *(V4*)&buf[0][40][sc] = VA;
            if (colC) *(V4*)&frames[(size_t)(GN - 1) * GN + gj0] = VA;
        }
    }
    __syncthreads();

    // ================= steps 1 .. NSTEPS-1 (smem ping-pong) =================
    #pragma unroll
    for (int s = 1; s < NSTEPS; ++s) {
        const float (*A)[COLS_P] = buf[(s + 1) & 1];
        float (*B)[COLS_P] = buf[s & 1];
        float* f0 = fr0 + (size_t)s * (GN * GN);
        const bool last = (s == NSTEPS - 1);

        V4 F0 = *(const V4*)&A[rbase + 0][sc];
        V4 F1 = *(const V4*)&A[rbase + 1][sc];
        V4 F2 = *(const V4*)&A[rbase + 2][sc];
        V4 F3 = *(const V4*)&A[rbase + 3][sc];
        float TlA = A[rbase + 1][sc - 1], TrA = A[rbase + 1][sc + 4];
        float TlB = A[rbase + 2][sc - 1], TrB = A[rbase + 2][sc + 4];

        V4 VA = rowcalc(F0, F1, F2, TlA, TrA);
        V4 VB = rowcalc(F1, F2, F3, TlB, TrB);

        if (!last) {
            *(V4*)&B[rbase + 1][sc] = VA;
            *(V4*)&B[rbase + 2][sc] = VB;
        }
        if (storeC) {
            *(V4*)&f0[0]  = VA;
            *(V4*)&f0[GN] = VB;
        }
        if (topFix) {               // global row 0 := row 1
            if (!last) *(V4*)&B[9][sc] = VB;
            if (colC) *(V4*)&frames[(size_t)s * (GN * GN) + gj0] = VB;
        }
        if (botFix) {               // global row 511 := row 510
            if (!last) *(V4*)&B[40][sc] = VA;
            if (colC) *(V4*)&frames[(size_t)s * (GN * GN) + (size_t)(GN - 1) * GN + gj0] = VA;
        }
        if (!last) __syncthreads();
    }

#if __CUDA_ARCH__ >= 900
    cudaTriggerProgrammaticLaunchCompletion();
#endif
}

static void launch_pdl(const void* func, const float* src, float* dst,
                       const float* k1, const float* k2,
                       const float* a1, const float* a2)
{
    cudaLaunchConfig_t cfg = {};
    cfg.gridDim  = dim3(GN / TBC, GN / TBR);   // 16 x 16 = 256 CTAs (2 per SM)
    cfg.blockDim = dim3(NT);
    cfg.dynamicSmemBytes = 0;
    cfg.stream = 0;
    cudaLaunchAttribute attr[1];
    attr[0].id = cudaLaunchAttributeProgrammaticStreamSerialization;
    attr[0].val.programmaticStreamSerializationAllowed = 1;
    cfg.attrs = attr;
    cfg.numAttrs = 1;
    void* args[] = { (void*)&src, (void*)&dst, (void*)&k1, (void*)&k2,
                     (void*)&a1, (void*)&a2 };
    cudaLaunchKernelExC(&cfg, func, args);
}

extern "C" void kernel_launch(void* const* d_in, const int* in_sizes, int n_in,
                              void* d_out, int out_size)
{
    (void)in_sizes; (void)n_in; (void)out_size;
    const float* u0 = (const float*)d_in[0];
    const float* k1 = (const float*)d_in[1];
    const float* k2 = (const float*)d_in[2];
    const float* a1 = (const float*)d_in[3];
    const float* a2 = (const float*)d_in[4];
    float* out = (float*)d_out;

    int done = 0;
    const float* src = u0;
    while (done < TOTAL_STEPS) {
        int steps = TOTAL_STEPS - done;
        if (steps >= TD) {
            launch_pdl((const void*)adr_chunk<TD>, src,
                       out + (size_t)done * GN * GN, k1, k2, a1, a2);
            steps = TD;
        } else {
            launch_pdl((const void*)adr_chunk<TD - 1>, src,
                       out + (size_t)done * GN * GN, k1, k2, a1, a2);
        }
        src = out + (size_t)(done + steps - 1) * GN * GN;
        done += steps;
    }
}

// round 16
// speedup vs baseline: 1.2030x; 1.1101x over previous
#include <cuda_runtime.h>
#include <cstring>

#define GN 512
#define TBR 64          // tile rows
#define TBC 32          // tile cols
#define TD 9            // frames per chunk: fused step 0 (exact region) + 8 eroding steps
#define ROWS_P 82       // padded smem rows (region 80 + ring)
#define COLS_P 56       // float stride: 2-row offset 112 = 16 mod 32 -> conflict-free LDS.128
#define NGRP 12         // 4-column groups per region (48 cols)
#define NT 480          // 12 groups x 40 two-row strips
#define TOTAL_STEPS 199

typedef unsigned long long u64;
typedef ulonglong2 V4;      // one smem row quad: .x = cols(0,1) packed, .y = cols(2,3)

__device__ __forceinline__ u64 PKf(float a, float b) {
    float2 t = make_float2(a, b); u64 r; memcpy(&r, &t, 8); return r;
}
__device__ __forceinline__ float2 UPf(u64 v) {
    float2 t; memcpy(&t, &v, 8); return t;
}
__device__ __forceinline__ u64 ADD2(u64 a, u64 b) {
    u64 d; asm("add.rn.f32x2 %0,%1,%2;" : "=l"(d) : "l"(a), "l"(b)); return d;
}
__device__ __forceinline__ u64 MUL2(u64 a, u64 b) {
    u64 d; asm("mul.rn.f32x2 %0,%1,%2;" : "=l"(d) : "l"(a), "l"(b)); return d;
}
__device__ __forceinline__ u64 FMA2(u64 a, u64 b, u64 c) {
    u64 d; asm("fma.rn.f32x2 %0,%1,%2,%3;" : "=l"(d) : "l"(a), "l"(b), "l"(c)); return d;
}

// new(i,j) = V(clamp(i,1,510), clamp(j,1,510)); state extended by clamp(.,0,511).
// 64x32 tiles -> 128 CTAs (one per SM). Thread = 4-col group x 2-row strip; full
// 80x48 region in a garbage-ringed smem buffer. Step 0 is FUSED with the global
// load (clamped LDG = true extended state), so the WHOLE region is exact after
// step 0 and ring erosion (1 cell/step) only starts at step 1 -> the central
// 64x32 (depth 8) is exact through 8 more steps: NINE frames per chunk, 23
// launches total (22x<9> + <1>). f32x2 math on LDS.128 pairs, branchless col
// specials, same-thread row fixups, last step skips STS+barrier, PDL chains
// chunks (preamble before the fence).
template <int NSTEPS>
__global__ __launch_bounds__(NT) void adr_chunk(
    const float* __restrict__ in_state,
    float* __restrict__ frames,
    const float* __restrict__ k1p, const float* __restrict__ k2p,
    const float* __restrict__ a1p, const float* __restrict__ a2p)
{
    __shared__ __align__(16) float buf[2][ROWS_P][COLS_P];

    // ---------- preamble: safe before the PDL fence ----------
    const float k1 = __ldg(k1p), k2 = __ldg(k2p);
    const float a1 = __ldg(a1p), a2 = __ldg(a2p);
    const float inv_k12 = 1.0f / (k1 + k2);
    const float inv_dx2 = 511.0f * 511.0f;
    const float inv_2dx = 255.5f;
    const float DTC = 1e-7f;

    const int by = blockIdx.y, bx = blockIdx.x;
    const int r0 = by * TBR - 8;               // halo 8 (ring erosion depth)
    const int c0 = bx * TBC - 8;
    const int g  = (int)threadIdx.x % NGRP;    // 4-col group 0..11
    const int ty = (int)threadIdx.x / NGRP;    // strip 0..39 (2 rows)
    const int rbase = ty * 2;
    const int gj0 = c0 + 4 * g;
    const int sc  = 4 * g + 4;                 // smem col (16B aligned)

    const float kap = (gj0 < 256) ? k1 : k2;   // 4 | 256: never straddles
    const float al  = (gj0 < 256) ? a1 : a2;

    const float A1c = DTC * al * inv_dx2;
    const u64 cA1    = PKf(A1c, A1c);
    const u64 c1M4A1 = PKf(1.0f - 4.0f * A1c, 1.0f - 4.0f * A1c);
    const u64 cM1    = PKf(-1.0f, -1.0f);
    const u64 cONE   = PKf(1.0f, 1.0f);
    const u64 cI2    = PKf(inv_2dx, inv_2dx);
    const u64 cMI2   = PKf(-inv_2dx, -inv_2dx);
    const u64 cB1    = PKf(DTC * kap, DTC * kap);

    const bool colC = (g >= 2) && (g <= 9);            // central 32 cols
    const bool rowC = (ty >= 4) && (ty <= 35);         // central 64 rows
    const bool storeC = colC && rowC;
    const bool isI  = (gj0 == 252);                    // group holding col 255
    const bool isL  = (gj0 == 0);
    const bool isR  = (gj0 == 508);                    // group holding col 511
    const bool topFix = (by == 0) && (ty == 4);            // global rows 0,1
    const bool botFix = (by == GN / TBR - 1) && (ty == 35); // global rows 510,511

    auto pointPair = [&](u64 Tm, u64 Tc, u64 Tp, u64 L, u64 R) -> u64 {
        u64 sum  = ADD2(ADD2(Tm, Tp), ADD2(L, R));
        u64 lapc = FMA2(Tc, c1M4A1, MUL2(sum, cA1));   // Tc + DT*al*lap
        u64 dxv  = FMA2(Tm, cM1, Tp);                   // Tp - Tm
        u64 dyv  = FMA2(L,  cM1, R);                    // R - L
        u64 P    = FMA2(dxv, cMI2, ADD2(Tc, cM1));      // (c-1) - T_x
        u64 Q    = FMA2(dyv, cI2,  cONE);               // T_y + 1
        u64 S    = FMA2(MUL2(Tc, Tc), P, MUL2(Tc, Q));  // c^2*P + c*Q
        return FMA2(S, cB1, lapc);
    };

    auto rowcalc = [&](V4 Fm, V4 Fc, V4 Fp, float TlS, float TrS) -> V4 {
        float2 cl = UPf(Fc.x);
        float2 ch = UPf(Fc.y);
        u64 L0 = PKf(TlS, cl.x);
        u64 M  = PKf(cl.y, ch.x);              // R of pair0 == L of pair1
        u64 R1 = PKf(ch.y, TrS);
        u64 v0 = pointPair(Fm.x, Fc.x, Fp.x, L0, M);
        u64 v1 = pointPair(Fm.y, Fc.y, Fp.y, M, R1);
        float2 vh = UPf(v1);
        float ifv = fmaf(k1, TrS, k2 * ch.x) * inv_k12;  // interface col 255
        vh.y = isI ? ifv : vh.y;
        vh.y = isR ? vh.x : vh.y;                         // col 511 := 510
        v1 = PKf(vh.x, vh.y);
        float2 vl = UPf(v0);
        vl.x = isL ? vl.y : vl.x;                         // col 0 := 1
        v0 = PKf(vl.x, vl.y);
        V4 out; out.x = v0; out.y = v1; return out;
    };

    float* const fr0 = frames + (ptrdiff_t)(r0 + rbase) * GN + gj0;

    const bool canVec = (gj0 >= 0) && (gj0 + 3 < GN);
    const int j0 = min(max(gj0 + 0, 0), GN - 1);
    const int j1 = min(max(gj0 + 1, 0), GN - 1);
    const int j2 = min(max(gj0 + 2, 0), GN - 1);
    const int j3 = min(max(gj0 + 3, 0), GN - 1);
    const int jl = min(max(gj0 - 1, 0), GN - 1);
    const int jr = min(max(gj0 + 4, 0), GN - 1);

    // ---------- PDL fence: predecessor's final frame must be visible ----------
#if __CUDA_ARCH__ >= 900
    cudaGridDependencySynchronize();
#endif

    // ================= fused global load + STEP 0 (region fully exact) =================
    {
        auto ldrow = [&](int gi) -> V4 {
            int li = min(max(gi, 0), GN - 1);
            if (canVec) return *(const V4*)&in_state[(size_t)li * GN + gj0];
            V4 v;
            v.x = PKf(in_state[(size_t)li * GN + j0], in_state[(size_t)li * GN + j1]);
            v.y = PKf(in_state[(size_t)li * GN + j2], in_state[(size_t)li * GN + j3]);
            return v;
        };
        auto lded = [&](int gi, int jj) -> float {
            int li = min(max(gi, 0), GN - 1);
            return in_state[(size_t)li * GN + jj];
        };

        V4 Fm = ldrow(r0 + rbase - 1);
        V4 F1 = ldrow(r0 + rbase);
        V4 F2 = ldrow(r0 + rbase + 1);
        V4 F3 = ldrow(r0 + rbase + 2);
        float TlA = lded(r0 + rbase,     jl), TrA = lded(r0 + rbase,     jr);
        float TlB = lded(r0 + rbase + 1, jl), TrB = lded(r0 + rbase + 1, jr);

        V4 VA = rowcalc(Fm, F1, F2, TlA, TrA);
        V4 VB = rowcalc(F1, F2, F3, TlB, TrB);

        if (NSTEPS > 1) {
            *(V4*)&buf[0][rbase + 1][sc] = VA;
            *(V4*)&buf[0][rbase + 2][sc] = VB;
        }
        if (storeC) {
            *(V4*)&fr0[0]  = VA;
            *(V4*)&fr0[GN] = VB;
        }
        if (topFix) {               // global row 0 := row 1
            if (NSTEPS > 1) *(V4*)&buf[0][9][sc] = VB;
            if (colC) *(V4*)&frames[gj0] = VB;
        }
        if (botFix) {               // global row 511 := row 510
            if (NSTEPS > 1) *(V4*)&buf[0][72][sc] = VA;
            if (colC) *(V4*)&frames[(size_t)(GN - 1) * GN + gj0] = VA;
        }
    }
    if (NSTEPS > 1) __syncthreads();

    // ================= steps 1 .. NSTEPS-1 (smem ping-pong; erosion 1 cell/step) =================
    #pragma unroll
    for (int s = 1; s < NSTEPS; ++s) {
        const float (*A)[COLS_P] = buf[(s + 1) & 1];
        float (*B)[COLS_P] = buf[s & 1];
        float* f0 = fr0 + (size_t)s * (GN * GN);
        const bool last = (s == NSTEPS - 1);

        V4 F0 = *(const V4*)&A[rbase + 0][sc];
        V4 F1 = *(const V4*)&A[rbase + 1][sc];
        V4 F2 = *(const V4*)&A[rbase + 2][sc];
        V4 F3 = *(const V4*)&A[rbase + 3][sc];
        float TlA = A[rbase + 1][sc - 1], TrA = A[rbase + 1][sc + 4];
        float TlB = A[rbase + 2][sc - 1], TrB = A[rbase + 2][sc + 4];

        V4 VA = rowcalc(F0, F1, F2, TlA, TrA);
        V4 VB = rowcalc(F1, F2, F3, TlB, TrB);

        if (!last) {
            *(V4*)&B[rbase + 1][sc] = VA;
            *(V4*)&B[rbase + 2][sc] = VB;
        }
        if (storeC) {
            *(V4*)&f0[0]  = VA;
            *(V4*)&f0[GN] = VB;
        }
        if (topFix) {               // global row 0 := row 1
            if (!last) *(V4*)&B[9][sc] = VB;
            if (colC) *(V4*)&frames[(size_t)s * (GN * GN) + gj0] = VB;
        }
        if (botFix) {               // global row 511 := row 510
            if (!last) *(V4*)&B[72][sc] = VA;
            if (colC) *(V4*)&frames[(size_t)s * (GN * GN) + (size_t)(GN - 1) * GN + gj0] = VA;
        }
        if (!last) __syncthreads();
    }

#if __CUDA_ARCH__ >= 900
    cudaTriggerProgrammaticLaunchCompletion();
#endif
}

static void launch_pdl(const void* func, const float* src, float* dst,
                       const float* k1, const float* k2,
                       const float* a1, const float* a2)
{
    cudaLaunchConfig_t cfg = {};
    cfg.gridDim  = dim3(GN / TBC, GN / TBR);   // 16 x 8 = 128 CTAs
    cfg.blockDim = dim3(NT);
    cfg.dynamicSmemBytes = 0;
    cfg.stream = 0;
    cudaLaunchAttribute attr[1];
    attr[0].id = cudaLaunchAttributeProgrammaticStreamSerialization;
    attr[0].val.programmaticStreamSerializationAllowed = 1;
    cfg.attrs = attr;
    cfg.numAttrs = 1;
    void* args[] = { (void*)&src, (void*)&dst, (void*)&k1, (void*)&k2,
                     (void*)&a1, (void*)&a2 };
    cudaLaunchKernelExC(&cfg, func, args);
}

extern "C" void kernel_launch(void* const* d_in, const int* in_sizes, int n_in,
                              void* d_out, int out_size)
{
    (void)in_sizes; (void)n_in; (void)out_size;
    const float* u0 = (const float*)d_in[0];
    const float* k1 = (const float*)d_in[1];
    const float* k2 = (const float*)d_in[2];
    const float* a1 = (const float*)d_in[3];
    const float* a2 = (const float*)d_in[4];
    float* out = (float*)d_out;

    int done = 0;
    const float* src = u0;
    while (done < TOTAL_STEPS) {
        int steps = TOTAL_STEPS - done;
        if (steps >= TD) {
            launch_pdl((const void*)adr_chunk<TD>, src,
                       out + (size_t)done * GN * GN, k1, k2, a1, a2);
            steps = TD;
        } else {
            // final remainder: 199 - 22*9 = 1 frame (fused step 0 only)
            launch_pdl((const void*)adr_chunk<1>, src,
                       out + (size_t)done * GN * GN, k1, k2, a1, a2);
            steps = 1;
        }
        src = out + (size_t)(done + steps - 1) * GN * GN;
        done += steps;
    }
}